// round 4
// baseline (speedup 1.0000x reference)
#include <cuda_runtime.h>
#include <cstdint>

#define NM 4
#define NB 64
#define NL 512
#define NQ 512
#define NS 26
#define NSL 32          // p-slices per model (CTAs per model)
#define PSL 16          // p states per slice
#define NTH 256

// SMEM layout (floats):
//  A_s   : 16 rows * 584          = 9344   (swizzled)
//  alp_s : 64 rows * 516          = 33024  (padded)
//  BemT_s: 26 * 16                = 416
//  pi_s  : 16
//  inp_s : 64 * 26                = 1664
#define SMEM_FLOATS (16*584 + 64*516 + 416 + 16 + 64*26)
#define SMEM_BYTES  (SMEM_FLOATS * 4)

// ---------------- device scratch (no runtime allocation allowed) ------------
__device__ float g_A[NM * NQ * NQ];
__device__ float g_pi[NM * NQ];
__device__ float g_Bem[NM * NQ * NS];
__device__ float g_alpha[NM * 2 * NB * NQ];   // double buffered, [m][buf][b][q]
__device__ float g_part[NM * NB * NSL];       // per-slice partial sums
__device__ int   g_ctr[NM * 32];              // padded per-model barrier counters

// ---------------- helpers ----------------------------------------------------
__device__ __forceinline__ void lds16(unsigned long long& a, unsigned long long& b,
                                      unsigned addr) {
    asm volatile("ld.shared.v2.u64 {%0, %1}, [%2];"
                 : "=l"(a), "=l"(b) : "r"(addr));
}
__device__ __forceinline__ void fma2(unsigned long long& d, unsigned long long a,
                                     unsigned long long x) {
    asm("fma.rn.f32x2 %0, %1, %2, %0;" : "+l"(d) : "l"(a), "l"(x));
}
__device__ __forceinline__ unsigned long long dup2(float x) {
    unsigned long long r; unsigned u = __float_as_uint(x);
    asm("mov.b64 %0, {%1, %1};" : "=l"(r) : "r"(u));
    return r;
}
__device__ __forceinline__ void unpk(unsigned long long v, float& lo, float& hi) {
    unsigned a, b;
    asm("mov.b64 {%0, %1}, %2;" : "=r"(a), "=r"(b) : "l"(v));
    lo = __uint_as_float(a); hi = __uint_as_float(b);
}
__device__ __forceinline__ void cp_async16(float* dst, const float* src) {
    unsigned d = (unsigned)__cvta_generic_to_shared(dst);
    asm volatile("cp.async.cg.shared.global [%0], [%1], 16;"
                 :: "r"(d), "l"(src) : "memory");
}
#define CP_COMMIT()  asm volatile("cp.async.commit_group;" ::: "memory")
#define CP_WAIT(n)   asm volatile("cp.async.wait_group %0;" :: "n"(n) : "memory")

// grid barrier for the 32 CTAs of one model (all CTAs resident: 1 CTA/SM, 128<=148)
__device__ __forceinline__ void gbar(int* c, int target) {
    __syncthreads();
    if (threadIdx.x == 0) {
        asm volatile("red.release.gpu.global.add.s32 [%0], 1;" :: "l"(c) : "memory");
        int v;
        do {
            asm volatile("ld.acquire.gpu.global.b32 %0, [%1];"
                         : "=r"(v) : "l"(c) : "memory");
        } while (v < target);
    }
    __syncthreads();
}

// ---------------- preprocessing: generic row softmax -------------------------
__global__ void sm_rows(const float* __restrict__ src, float* __restrict__ dst,
                        int rowlen) {
    int row = blockIdx.x;
    const float* x = src + (size_t)row * rowlen;
    float* y = dst + (size_t)row * rowlen;
    __shared__ float red[NTH];
    int tid = threadIdx.x;

    float mx = -1e30f;
    for (int i = tid; i < rowlen; i += NTH) mx = fmaxf(mx, x[i]);
    red[tid] = mx; __syncthreads();
    for (int o = NTH / 2; o > 0; o >>= 1) {
        if (tid < o) red[tid] = fmaxf(red[tid], red[tid + o]);
        __syncthreads();
    }
    mx = red[0]; __syncthreads();

    float sm = 0.f;
    for (int i = tid; i < rowlen; i += NTH) sm += expf(x[i] - mx);
    red[tid] = sm; __syncthreads();
    for (int o = NTH / 2; o > 0; o >>= 1) {
        if (tid < o) red[tid] += red[tid + o];
        __syncthreads();
    }
    float inv = 1.0f / red[0];
    for (int i = tid; i < rowlen; i += NTH) y[i] = expf(x[i] - mx) * inv;
}

__global__ void zero_k() {
    int i = threadIdx.x;
    if (i < NM * 32) g_ctr[i] = 0;
}

// ---------------- main persistent forward kernel -----------------------------
// grid 128 = 4 models x 32 slices; 256 threads: tid = b*4 + pg,
// thread owns (batch b, 4 consecutive p = slice*16 + pg*4 .. +3).
__global__ void __launch_bounds__(NTH, 1)
hmm_fwd(const float* __restrict__ inputs, float* __restrict__ out) {
    const int m     = blockIdx.x >> 5;
    const int slice = blockIdx.x & 31;
    const int p0    = slice * PSL;
    const int tid   = threadIdx.x;
    const int b     = tid >> 2;
    const int pg    = tid & 3;

    extern __shared__ float smf[];
    float* A_s    = smf;                 // 16 * 584
    float* alp_s  = A_s + 16 * 584;      // 64 * 516
    float* BemT_s = alp_s + 64 * 516;    // 26 * 16  ([s][p])
    float* pi_s   = BemT_s + 26 * 16;    // 16
    float* inp_s  = pi_s + 16;           // 64 * 26  ([b][s])

    // ---- one-time SMEM init ----
    {
        const float* Ag = g_A + (size_t)m * NQ * NQ + p0;   // A[m][q][p0+..]
        for (int i = tid; i < PSL * NQ; i += NTH) {
            int p = i >> 9, q = i & (NQ - 1);
            int c = q >> 2, r = q & 3;
            int sp = p + (p >> 2);
            A_s[p * 584 + (c + sp) * 4 + r] = Ag[(size_t)q * NQ + p];
        }
        const float* Bg = g_Bem + ((size_t)m * NQ + p0) * NS;
        for (int i = tid; i < PSL * NS; i += NTH) {
            int p = i / NS, s = i - p * NS;
            BemT_s[s * PSL + p] = Bg[(size_t)p * NS + s];
        }
        if (tid < PSL) pi_s[tid] = g_pi[m * NQ + p0 + tid];
    }

    // per-thread bases
    unsigned alp_u = (unsigned)__cvta_generic_to_shared(alp_s + b * 516);
    unsigned Au0, Au1, Au2, Au3;
    {
        int p = pg * 4;
        Au0 = (unsigned)__cvta_generic_to_shared(A_s + (p+0) * 584 + ((p+0) + ((p+0)>>2)) * 4);
        Au1 = (unsigned)__cvta_generic_to_shared(A_s + (p+1) * 584 + ((p+1) + ((p+1)>>2)) * 4);
        Au2 = (unsigned)__cvta_generic_to_shared(A_s + (p+2) * 584 + ((p+2) + ((p+2)>>2)) * 4);
        Au3 = (unsigned)__cvta_generic_to_shared(A_s + (p+3) * 584 + ((p+3) + ((p+3)>>2)) * 4);
    }
    const int   q_out  = p0 + pg * 4;
    float*      gal0   = g_alpha + (size_t)(m * 2 + 0) * NB * NQ;
    float*      gal1   = g_alpha + (size_t)(m * 2 + 1) * NB * NQ;
    const float* inp_m = inputs + (size_t)m * NB * NL * NS;
    float*      part_b = g_part + (m * NB + b) * NSL;
    int*        ctr    = &g_ctr[m * 32];
    const bool  lead   = (slice == 0) && (pg == 0);
    float ll = 0.f;

    // ---- t = 0 : alpha0 = pi * e0 ----
    {
        const float* it = inp_m;   // t = 0
        for (int i = tid; i < NB * NS; i += NTH) {
            int bb = i / NS, s = i - bb * NS;
            inp_s[i] = __ldg(it + (size_t)bb * (NL * NS) + s);
        }
        __syncthreads();

        unsigned long long eA = 0ull, eB = 0ull;
        const float* xb = inp_s + b * NS;
        const float* bt = BemT_s + pg * 4;
        unsigned bt_u = (unsigned)__cvta_generic_to_shared(bt);
        #pragma unroll
        for (int s = 0; s < NS; ++s) {
            unsigned long long x2 = dup2(xb[s]);
            unsigned long long b01, b23;
            lds16(b01, b23, bt_u + s * PSL * 4);
            fma2(eA, b01, x2); fma2(eB, b23, x2);
        }
        float e0, e1, e2, e3;
        unpk(eA, e0, e1); unpk(eB, e2, e3);

        float4 ov;
        ov.x = pi_s[pg * 4 + 0] * e0;
        ov.y = pi_s[pg * 4 + 1] * e1;
        ov.z = pi_s[pg * 4 + 2] * e2;
        ov.w = pi_s[pg * 4 + 3] * e3;
        *(float4*)(gal0 + (size_t)b * NQ + q_out) = ov;
        gbar(ctr, 32);
    }

    // ---- t = 1 .. 511 ----
    #pragma unroll 1
    for (int t = 1; t < NL; ++t) {
        const float* src = (t & 1) ? gal0 : gal1;
        float*       dst = (t & 1) ? gal1 : gal0;

        // stage inputs for step t
        {
            const float* it = inp_m + (size_t)t * NS;
            for (int i = tid; i < NB * NS; i += NTH) {
                int bb = i / NS, s = i - bb * NS;
                inp_s[i] = __ldg(it + (size_t)bb * (NL * NS) + s);
            }
        }
        // async stage alpha (two q-chunks, L2-coherent)
        #pragma unroll
        for (int h = 0; h < 2; ++h) {
            #pragma unroll
            for (int j = 0; j < 16; ++j) {
                int idx4 = j * NTH + tid;
                int bb = idx4 >> 6;
                int q  = h * 256 + ((idx4 & 63) << 2);
                cp_async16(alp_s + bb * 516 + q, src + (size_t)bb * NQ + q);
            }
            CP_COMMIT();
        }

        unsigned long long acc0 = 0ull, acc1 = 0ull, acc2 = 0ull, acc3 = 0ull;
        CP_WAIT(1);
        __syncthreads();

        // emission for step t (inp_s ready)
        float e0, e1, e2, e3;
        {
            unsigned long long eA = 0ull, eB = 0ull;
            const float* xb = inp_s + b * NS;
            unsigned bt_u = (unsigned)__cvta_generic_to_shared(BemT_s + pg * 4);
            #pragma unroll
            for (int s = 0; s < NS; ++s) {
                unsigned long long x2 = dup2(xb[s]);
                unsigned long long b01, b23;
                lds16(b01, b23, bt_u + s * PSL * 4);
                fma2(eA, b01, x2); fma2(eB, b23, x2);
            }
            unpk(eA, e0, e1); unpk(eB, e2, e3);
        }

        // chunk 0: q in [0,256)
        {
            unsigned xo = alp_u, A0 = Au0, A1 = Au1, A2 = Au2, A3 = Au3;
            #pragma unroll 8
            for (int c = 0; c < 64; ++c) {
                unsigned long long x0, x1, a0, a1;
                lds16(x0, x1, xo + c * 16);
                lds16(a0, a1, A0 + c * 16); fma2(acc0, a0, x0); fma2(acc0, a1, x1);
                lds16(a0, a1, A1 + c * 16); fma2(acc1, a0, x0); fma2(acc1, a1, x1);
                lds16(a0, a1, A2 + c * 16); fma2(acc2, a0, x0); fma2(acc2, a1, x1);
                lds16(a0, a1, A3 + c * 16); fma2(acc3, a0, x0); fma2(acc3, a1, x1);
            }
        }
        CP_WAIT(0);
        __syncthreads();
        // chunk 1: q in [256,512)
        {
            unsigned xo = alp_u + 1024, A0 = Au0 + 1024, A1 = Au1 + 1024,
                     A2 = Au2 + 1024, A3 = Au3 + 1024;
            #pragma unroll 8
            for (int c = 0; c < 64; ++c) {
                unsigned long long x0, x1, a0, a1;
                lds16(x0, x1, xo + c * 16);
                lds16(a0, a1, A0 + c * 16); fma2(acc0, a0, x0); fma2(acc0, a1, x1);
                lds16(a0, a1, A1 + c * 16); fma2(acc1, a0, x0); fma2(acc1, a1, x1);
                lds16(a0, a1, A2 + c * 16); fma2(acc2, a0, x0); fma2(acc2, a1, x1);
                lds16(a0, a1, A3 + c * 16); fma2(acc3, a0, x0); fma2(acc3, a1, x1);
            }
        }

        // finalize: r = acc_even + acc_odd; alpha = r * e * (1/s on rescale steps)
        float r0, r1, r2, r3, hx, hy;
        unpk(acc0, hx, hy); r0 = hx + hy;
        unpk(acc1, hx, hy); r1 = hx + hy;
        unpk(acc2, hx, hy); r2 = hx + hy;
        unpk(acc3, hx, hy); r3 = hx + hy;

        float sc = 1.f;
        if ((t & 15) == 0) {               // t = 16,32,...,496: apply deferred 1/s
            float s = 0.f;
            const float4* pp = (const float4*)part_b;
            #pragma unroll
            for (int k = 0; k < 8; ++k) {
                float4 v = __ldcg(pp + k);
                s += (v.x + v.y) + (v.z + v.w);
            }
            sc = 1.0f / s;
            if (lead) ll += logf(s);
        }

        float o0 = r0 * e0 * sc, o1 = r1 * e1 * sc;
        float o2 = r2 * e2 * sc, o3 = r3 * e3 * sc;
        float4 ov; ov.x = o0; ov.y = o1; ov.z = o2; ov.w = o3;
        *(float4*)(dst + (size_t)b * NQ + q_out) = ov;

        if ((t & 15) == 15) {              // publish slice partial sums
            float v = (o0 + o1) + (o2 + o3);
            v += __shfl_xor_sync(0xffffffffu, v, 1);
            v += __shfl_xor_sync(0xffffffffu, v, 2);
            if (pg == 0) part_b[slice] = v;
        }
        gbar(ctr, 32 * (t + 1));
    }

    // ---- finalize loglik ----
    if (lead) {
        float s = 0.f;
        const float4* pp = (const float4*)part_b;
        #pragma unroll
        for (int k = 0; k < 8; ++k) {
            float4 v = __ldcg(pp + k);
            s += (v.x + v.y) + (v.z + v.w);
        }
        out[m * NB + b] = ll + logf(s);
    }
}

// ---------------- launch ------------------------------------------------------
extern "C" void kernel_launch(void* const* d_in, const int* in_sizes, int n_in,
                              void* d_out, int out_size) {
    (void)in_sizes; (void)n_in; (void)out_size;
    const float* inputs      = (const float*)d_in[0];
    const float* A_logits    = (const float*)d_in[1];
    const float* init_logits = (const float*)d_in[2];
    const float* em_logits   = (const float*)d_in[3];
    float* out = (float*)d_out;

    float *pA, *ppi, *pB;
    cudaGetSymbolAddress((void**)&pA,  g_A);
    cudaGetSymbolAddress((void**)&ppi, g_pi);
    cudaGetSymbolAddress((void**)&pB,  g_Bem);

    cudaFuncSetAttribute(hmm_fwd, cudaFuncAttributeMaxDynamicSharedMemorySize,
                         SMEM_BYTES);

    zero_k<<<1, 128>>>();
    sm_rows<<<NM * NQ, NTH>>>(A_logits, pA, NQ);
    sm_rows<<<NM,      NTH>>>(init_logits, ppi, NQ);
    sm_rows<<<NM * NQ, NTH>>>(em_logits, pB, NS);
    hmm_fwd<<<NM * NSL, NTH, SMEM_BYTES>>>(inputs, out);
}